// round 4
// baseline (speedup 1.0000x reference)
#include <cuda_runtime.h>
#include <cstdint>
#include <cstddef>

typedef unsigned long long u64;

#define KDIM 3072
#define FDIM 512
#define VDIM 128
#define NBATCH 32
#define NN 256
#define BN 8192
#define TEMP 11.3137084989847606f  // sqrt(128)

// ---------------- device scratch ----------------
static __device__ float g_fc1T[FDIM * VDIM];
static __device__ float g_bc[VDIM];
static __device__ float g_wcp[4][KDIM * VDIM];
static __device__ float g_WcT[KDIM * VDIM];
static __device__ float g_vp[2][(size_t)BN * VDIM];
static __device__ float g_fn[(size_t)BN * VDIM];
static __device__ float g_cm[NBATCH * NN];
static __device__ float g_F1[NBATCH * NN];
static __device__ float g_F2[NBATCH * NN];
static __device__ float g_lp[NBATCH];

// ---------------- packed f32x2 helpers ----------------
__device__ __forceinline__ u64 splat2(float a) {
    u64 r; asm("mov.b64 %0,{%1,%1};" : "=l"(r) : "f"(a)); return r;
}
__device__ __forceinline__ void ffma2(u64& c, u64 a, u64 b) {
    asm("fma.rn.f32x2 %0,%1,%2,%0;" : "+l"(c) : "l"(a), "l"(b));
}
__device__ __forceinline__ float2 unpack2(u64 c) {
    float2 r; asm("mov.b64 {%0,%1},%2;" : "=f"(r.x), "=f"(r.y) : "l"(c)); return r;
}

// ---------------- prep ----------------
__global__ void k_prep_fc1T(const float* __restrict__ fc1_w) {
    int idx = blockIdx.x * 256 + threadIdx.x;       // 65536
    int o = idx >> 7, v = idx & 127;
    g_fc1T[idx] = fc1_w[v * FDIM + o];
}

__global__ void k_bc(const float* __restrict__ fc1_w,
                     const float* __restrict__ conv_b,
                     const float* __restrict__ fc1_b) {
    int v = threadIdx.x;                             // 128
    float s = fc1_b[v];
    for (int o = 0; o < FDIM; o++) s += fc1_w[v * FDIM + o] * conv_b[o];
    g_bc[v] = s;
}

// ---------------- Wc GEMM: WcT[k3][v] = sum_o conv_w[o][k3]*fc1T[o][v] ----------------
// M=3072, N=128, K=512, split-K=4, tile 128x128
__global__ void __launch_bounds__(256) k_wc_gemm(const float* __restrict__ conv_w) {
    __shared__ float As[2][16][128];
    __shared__ float Bs[2][16][128];
    int tid = threadIdx.x;
    int mb = blockIdx.x * 128;
    int ks = blockIdx.y;
    int tx = tid & 15, ty = tid >> 4;
    int lo = tid >> 5, lq = tid & 31;
    const float* gA = conv_w + (size_t)(ks * 128) * KDIM + mb;
    const float* gB = g_fc1T + (size_t)(ks * 128) * VDIM;
    float4 pa0, pa1, pb0, pb1;
    auto loadG = [&](int it) {
        pa0 = *(const float4*)(gA + (size_t)(it * 16 + lo) * KDIM + lq * 4);
        pa1 = *(const float4*)(gA + (size_t)(it * 16 + lo + 8) * KDIM + lq * 4);
        pb0 = *(const float4*)(gB + (it * 16 + lo) * VDIM + lq * 4);
        pb1 = *(const float4*)(gB + (it * 16 + lo + 8) * VDIM + lq * 4);
    };
    auto storeS = [&](int buf) {
        *(float4*)&As[buf][lo][lq * 4] = pa0;
        *(float4*)&As[buf][lo + 8][lq * 4] = pa1;
        *(float4*)&Bs[buf][lo][lq * 4] = pb0;
        *(float4*)&Bs[buf][lo + 8][lq * 4] = pb1;
    };
    loadG(0); storeS(0); __syncthreads();
    u64 c[32];
#pragma unroll
    for (int i = 0; i < 32; i++) c[i] = 0ull;
    const int NIT = 8;
    for (int it = 0; it < NIT; ++it) {
        int cur = it & 1;
        if (it + 1 < NIT) loadG(it + 1);
#pragma unroll
        for (int kk = 0; kk < 16; kk++) {
            float4 af0 = *(float4*)&As[cur][kk][ty * 8];
            float4 af1 = *(float4*)&As[cur][kk][ty * 8 + 4];
            float4 bf0 = *(float4*)&Bs[cur][kk][tx * 8];
            float4 bf1 = *(float4*)&Bs[cur][kk][tx * 8 + 4];
            u64 b[4] = { *(u64*)&bf0.x, *(u64*)&bf0.z, *(u64*)&bf1.x, *(u64*)&bf1.z };
            float a[8] = { af0.x, af0.y, af0.z, af0.w, af1.x, af1.y, af1.z, af1.w };
#pragma unroll
            for (int mi = 0; mi < 8; mi++) {
                u64 as = splat2(a[mi]);
#pragma unroll
                for (int p = 0; p < 4; p++) ffma2(c[mi * 4 + p], as, b[p]);
            }
        }
        if (it + 1 < NIT) { storeS((it + 1) & 1); __syncthreads(); }
    }
    float* out = g_wcp[ks];
#pragma unroll
    for (int mi = 0; mi < 8; mi++) {
        float2* orow = (float2*)(out + (size_t)(mb + ty * 8 + mi) * VDIM);
#pragma unroll
        for (int p = 0; p < 4; p++) orow[tx * 4 + p] = unpack2(c[mi * 4 + p]);
    }
}

__global__ void k_wc_combine() {
    int idx = blockIdx.x * 256 + threadIdx.x;        // 393216
    g_WcT[idx] = g_wcp[0][idx] + g_wcp[1][idx] + g_wcp[2][idx] + g_wcp[3][idx];
}

// ---------------- main GEMM: v = X @ WcT  (M=8192,N=128,K=3072), split-K=2 ----------------
__global__ void __launch_bounds__(256) k_gemm_main(const float* __restrict__ X) {
    __shared__ float As[2][128][20];
    __shared__ float Bs[2][16][128];
    int tid = threadIdx.x;
    int mb = blockIdx.x * 128;
    int ks = blockIdx.y;
    int tx = tid & 15, ty = tid >> 4;
    int ar = tid >> 1, ah = tid & 1;
    const float* gA = X + (size_t)(mb + ar) * KDIM + ks * 1536 + ah * 8;
    int bkk = tid >> 5, bq = tid & 31;
    const float* gB = g_WcT + (size_t)(ks * 1536) * VDIM;
    float4 pa0, pa1, pb0, pb1;
    auto loadG = [&](int it) {
        pa0 = *(const float4*)(gA + it * 16);
        pa1 = *(const float4*)(gA + it * 16 + 4);
        pb0 = *(const float4*)(gB + (size_t)(it * 16 + bkk) * VDIM + bq * 4);
        pb1 = *(const float4*)(gB + (size_t)(it * 16 + bkk + 8) * VDIM + bq * 4);
    };
    auto storeS = [&](int buf) {
        *(float4*)&As[buf][ar][ah * 8] = pa0;
        *(float4*)&As[buf][ar][ah * 8 + 4] = pa1;
        *(float4*)&Bs[buf][bkk][bq * 4] = pb0;
        *(float4*)&Bs[buf][bkk + 8][bq * 4] = pb1;
    };
    loadG(0); storeS(0); __syncthreads();
    u64 c[32];
#pragma unroll
    for (int i = 0; i < 32; i++) c[i] = 0ull;
    const int NIT = 96;
    for (int it = 0; it < NIT; ++it) {
        int cur = it & 1;
        if (it + 1 < NIT) loadG(it + 1);
#pragma unroll
        for (int kk = 0; kk < 16; kk++) {
            float4 bf0 = *(float4*)&Bs[cur][kk][tx * 8];
            float4 bf1 = *(float4*)&Bs[cur][kk][tx * 8 + 4];
            u64 b[4] = { *(u64*)&bf0.x, *(u64*)&bf0.z, *(u64*)&bf1.x, *(u64*)&bf1.z };
#pragma unroll
            for (int mi = 0; mi < 8; mi++) {
                u64 as = splat2(As[cur][ty * 8 + mi][kk]);
#pragma unroll
                for (int p = 0; p < 4; p++) ffma2(c[mi * 4 + p], as, b[p]);
            }
        }
        if (it + 1 < NIT) { storeS((it + 1) & 1); __syncthreads(); }
    }
    float* out = g_vp[ks];
#pragma unroll
    for (int mi = 0; mi < 8; mi++) {
        float2* orow = (float2*)(out + (size_t)(mb + ty * 8 + mi) * VDIM);
#pragma unroll
        for (int p = 0; p < 4; p++) orow[tx * 4 + p] = unpack2(c[mi * 4 + p]);
    }
}

// ---------------- combine split-K + bias, write f, L2-normalize ----------------
__global__ void k_combine(float* __restrict__ f_out) {
    int row = blockIdx.x;
    int v = threadIdx.x;                             // 128
    size_t i = (size_t)row * VDIM + v;
    float x = g_vp[0][i] + g_vp[1][i] + g_bc[v];
    f_out[i] = x;
    float ss = x * x;
#pragma unroll
    for (int o = 16; o > 0; o >>= 1) ss += __shfl_xor_sync(0xffffffffu, ss, o);
    __shared__ float sred[4];
    if ((v & 31) == 0) sred[v >> 5] = ss;
    __syncthreads();
    float tot = sred[0] + sred[1] + sred[2] + sred[3];
    float inv = 1.0f / fmaxf(sqrtf(tot), 1e-12f);
    g_fn[i] = x * inv;
}

// ---------------- affinity: A[b] = fn fn^T, symmetric (3 tiles of 4) ----------------
__global__ void __launch_bounds__(256) k_aff(float* __restrict__ A_out) {
    __shared__ float As[2][128][20];
    __shared__ float Bs[2][16][132];
    int t = blockIdx.x;                  // 0:(0,0) 1:(1,1) 2:(0,1)+mirror
    int b = blockIdx.y;
    int mb = (t == 1) ? 128 : 0;
    int nb = (t == 0) ? 0 : 128;
    const float* fb = g_fn + (size_t)b * NN * VDIM;
    int tid = threadIdx.x, tx = tid & 15, ty = tid >> 4;
    int ar = tid >> 1, ah = tid & 1;
    const float* gA = fb + (size_t)(mb + ar) * VDIM + ah * 8;
    const float* gB = fb + (size_t)(nb + ar) * VDIM + ah * 8;
    float4 pa0, pa1, pb0, pb1;
    auto loadG = [&](int it) {
        pa0 = *(const float4*)(gA + it * 16);
        pa1 = *(const float4*)(gA + it * 16 + 4);
        pb0 = *(const float4*)(gB + it * 16);
        pb1 = *(const float4*)(gB + it * 16 + 4);
    };
    auto storeS = [&](int buf) {
        *(float4*)&As[buf][ar][ah * 8] = pa0;
        *(float4*)&As[buf][ar][ah * 8 + 4] = pa1;
        Bs[buf][ah * 8 + 0][ar] = pb0.x;  Bs[buf][ah * 8 + 1][ar] = pb0.y;
        Bs[buf][ah * 8 + 2][ar] = pb0.z;  Bs[buf][ah * 8 + 3][ar] = pb0.w;
        Bs[buf][ah * 8 + 4][ar] = pb1.x;  Bs[buf][ah * 8 + 5][ar] = pb1.y;
        Bs[buf][ah * 8 + 6][ar] = pb1.z;  Bs[buf][ah * 8 + 7][ar] = pb1.w;
    };
    loadG(0); storeS(0); __syncthreads();
    u64 c[32];
#pragma unroll
    for (int i = 0; i < 32; i++) c[i] = 0ull;
    const int NIT = 8;
    for (int it = 0; it < NIT; ++it) {
        int cur = it & 1;
        if (it + 1 < NIT) loadG(it + 1);
#pragma unroll
        for (int kk = 0; kk < 16; kk++) {
            float4 bf0 = *(float4*)&Bs[cur][kk][tx * 8];
            float4 bf1 = *(float4*)&Bs[cur][kk][tx * 8 + 4];
            u64 b2[4] = { *(u64*)&bf0.x, *(u64*)&bf0.z, *(u64*)&bf1.x, *(u64*)&bf1.z };
#pragma unroll
            for (int mi = 0; mi < 8; mi++) {
                u64 as = splat2(As[cur][ty * 8 + mi][kk]);
#pragma unroll
                for (int p = 0; p < 4; p++) ffma2(c[mi * 4 + p], as, b2[p]);
            }
        }
        if (it + 1 < NIT) { storeS((it + 1) & 1); __syncthreads(); }
    }
    float* Ab = A_out + (size_t)b * NN * NN;
#pragma unroll
    for (int mi = 0; mi < 8; mi++) {
        int m = mb + ty * 8 + mi;
#pragma unroll
        for (int p = 0; p < 4; p++) {
            float2 val = unpack2(c[mi * 4 + p]);
            int n = nb + tx * 8 + 2 * p;
            *(float2*)&Ab[(size_t)m * NN + n] = val;
            if (t == 2) {
                Ab[(size_t)n * NN + m] = val.x;
                Ab[(size_t)(n + 1) * NN + m] = val.y;
            }
        }
    }
}

// ---------------- per-column stats: cm, 1/W1, 1/W2 ----------------
// A symmetric -> column stats == row stats; softmax 1/S cancels in L1 renorm.
__global__ void k_stats(const float* __restrict__ A_out,
                        const float* __restrict__ drop1,
                        const float* __restrict__ drop2) {
    int b = blockIdx.x, i = threadIdx.x;             // 256
    const float* Ab = A_out + (size_t)b * NN * NN;
    const float* d1 = drop1 + (size_t)b * NN * NN;
    const float* d2 = drop2 + (size_t)b * NN * NN;
    float mx = -1e30f;
    for (int k = 0; k < NN; k++) mx = fmaxf(mx, Ab[k * NN + i]);
    float cm = TEMP * mx;
    float W1 = 0.f, W2 = 0.f;
    for (int k = 0; k < NN; k++) {
        float e = __expf(TEMP * Ab[k * NN + i] - cm);
        if (k != i) {
            W1 += e * d1[k * NN + i];
            W2 += e * d2[k * NN + i];
        }
    }
    g_cm[b * NN + i] = cm;
    g_F1[b * NN + i] = 1.0f / fmaxf(W1, 1e-30f);
    g_F2[b * NN + i] = 1.0f / fmaxf(W2, 1e-30f);
}

// ---------------- loss: diag_i = F1_i * sum_{k!=i} e^{2s_ik-cm_k-cm_i} d2[i,k] d1[k,i] F2_k
__global__ void k_loss(const float* __restrict__ A_out,
                       const float* __restrict__ drop1,
                       const float* __restrict__ drop2) {
    __shared__ float sd2t[32 * 257];
    __shared__ float sred[8];
    int b = blockIdx.x, i = threadIdx.x;             // 256
    const float* Ab = A_out + (size_t)b * NN * NN;
    const float* d1 = drop1 + (size_t)b * NN * NN;
    const float* d2 = drop2 + (size_t)b * NN * NN;
    float cmi = g_cm[b * NN + i];
    float acc = 0.f;
    for (int k0 = 0; k0 < NN; k0 += 32) {
        __syncthreads();
        for (int t = i; t < 256 * 32; t += 256) {
            int r = t >> 5, kk = t & 31;
            sd2t[kk * 257 + r] = d2[r * NN + k0 + kk];   // coalesced load, transposed store
        }
        __syncthreads();
#pragma unroll 4
        for (int kk = 0; kk < 32; kk++) {
            int k = k0 + kk;
            float a = Ab[k * NN + i];                    // A symmetric: A[i][k]
            float e = __expf(2.0f * TEMP * a - g_cm[b * NN + k] - cmi);
            float term = e * sd2t[kk * 257 + i] * d1[k * NN + i] * g_F2[b * NN + k];
            acc += (k != i) ? term : 0.f;
        }
    }
    float val = g_F1[b * NN + i] * acc;
#pragma unroll
    for (int o = 16; o > 0; o >>= 1) val += __shfl_xor_sync(0xffffffffu, val, o);
    if ((i & 31) == 0) sred[i >> 5] = val;
    __syncthreads();
    if (i == 0) {
        float s = 0.f;
#pragma unroll
        for (int w = 0; w < 8; w++) s += sred[w];
        g_lp[b] = s;
    }
}

__global__ void k_final(float* __restrict__ out_loss) {
    float s = 0.f;
    for (int b = 0; b < NBATCH; b++) s += g_lp[b];
    out_loss[0] = -s / (float)(NBATCH * NN);
}

// ---------------- launch ----------------
extern "C" void kernel_launch(void* const* d_in, const int* in_sizes, int n_in,
                              void* d_out, int out_size) {
    const float* x      = (const float*)d_in[0];
    const float* conv_w = (const float*)d_in[1];
    const float* conv_b = (const float*)d_in[2];
    const float* fc1_w  = (const float*)d_in[3];
    const float* fc1_b  = (const float*)d_in[4];
    const float* drop1  = (const float*)d_in[5];
    const float* drop2  = (const float*)d_in[6];
    float* out_f = (float*)d_out;
    float* out_A = out_f + (size_t)BN * VDIM;
    float* out_loss = out_A + (size_t)NBATCH * NN * NN;

    k_prep_fc1T<<<256, 256>>>(fc1_w);
    k_bc<<<1, 128>>>(fc1_w, conv_b, fc1_b);
    k_wc_gemm<<<dim3(24, 4), 256>>>(conv_w);
    k_wc_combine<<<1536, 256>>>();
    k_gemm_main<<<dim3(64, 2), 256>>>(x);
    k_combine<<<BN, 128>>>(out_f);
    k_aff<<<dim3(3, NBATCH), 256>>>(out_A);
    k_stats<<<NBATCH, 256>>>(out_A, drop1, drop2);
    k_loss<<<NBATCH, 256>>>(out_A, drop1, drop2);
    k_final<<<1, 1>>>(out_loss);
}

// round 6
// speedup vs baseline: 2.0083x; 2.0083x over previous
#include <cuda_runtime.h>
#include <cuda_bf16.h>
#include <cstdint>
#include <cstddef>

typedef unsigned long long u64;

#define KDIM 3072
#define FDIM 512
#define VDIM 128
#define NBATCH 32
#define NN 256
#define BN 8192
#define TEMP 11.3137084989847606f  // sqrt(128)

// ---------------- device scratch ----------------
static __device__ float g_fc1T[FDIM * VDIM];
static __device__ float g_bc[VDIM];
static __device__ float g_wcp[4][KDIM * VDIM];
static __device__ __nv_bfloat16 g_Wc_hi[(size_t)VDIM * KDIM];   // [v][k]
static __device__ __nv_bfloat16 g_Wc_lo[(size_t)VDIM * KDIM];   // [v][k]
static __device__ float g_vp[2][(size_t)BN * VDIM];
static __device__ float g_fn[(size_t)BN * VDIM];
static __device__ float g_E[(size_t)NBATCH * NN * NN];          // exp(TEMP*A)
static __device__ float g_d2T[(size_t)NBATCH * NN * NN];
static __device__ float g_F1[NBATCH * NN];
static __device__ float g_F2[NBATCH * NN];
static __device__ float g_lp2[NBATCH * 8];

// ---------------- packed f32x2 helpers (SIMT GEMMs) ----------------
__device__ __forceinline__ u64 splat2(float a) {
    u64 r; asm("mov.b64 %0,{%1,%1};" : "=l"(r) : "f"(a)); return r;
}
__device__ __forceinline__ void ffma2(u64& c, u64 a, u64 b) {
    asm("fma.rn.f32x2 %0,%1,%2,%0;" : "+l"(c) : "l"(a), "l"(b));
}
__device__ __forceinline__ float2 unpack2(u64 c) {
    float2 r; asm("mov.b64 {%0,%1},%2;" : "=f"(r.x), "=f"(r.y) : "l"(c)); return r;
}

// ---------------- mma.sync helpers (plain PTX, sm_80+) ----------------
__device__ __forceinline__ uint32_t smem_u32(const void* p) {
    uint32_t a;
    asm("{ .reg .u64 t; cvta.to.shared.u64 t, %1; cvt.u32.u64 %0, t; }" : "=r"(a) : "l"(p));
    return a;
}
__device__ __forceinline__ uint32_t swz(uint32_t o) { return o ^ ((o >> 3) & 0x70); }

__device__ __forceinline__ void ldsm4(uint32_t& r0, uint32_t& r1, uint32_t& r2, uint32_t& r3,
                                      uint32_t addr) {
    asm volatile("ldmatrix.sync.aligned.m8n8.x4.shared.b16 {%0,%1,%2,%3}, [%4];"
                 : "=r"(r0), "=r"(r1), "=r"(r2), "=r"(r3) : "r"(addr));
}
__device__ __forceinline__ void mma16816(float* c, const uint32_t* a, uint32_t b0, uint32_t b1) {
    asm volatile("mma.sync.aligned.m16n8k16.row.col.f32.bf16.bf16.f32 "
                 "{%0,%1,%2,%3}, {%4,%5,%6,%7}, {%8,%9}, {%0,%1,%2,%3};"
                 : "+f"(c[0]), "+f"(c[1]), "+f"(c[2]), "+f"(c[3])
                 : "r"(a[0]), "r"(a[1]), "r"(a[2]), "r"(a[3]), "r"(b0), "r"(b1));
}

// ---------------- prep ----------------
__global__ void k_prep_fc1T(const float* __restrict__ fc1_w) {
    int idx = blockIdx.x * 256 + threadIdx.x;       // 65536
    int o = idx >> 7, v = idx & 127;
    g_fc1T[idx] = fc1_w[v * FDIM + o];
}

__global__ void k_bc(const float* __restrict__ fc1_w,
                     const float* __restrict__ conv_b,
                     const float* __restrict__ fc1_b) {
    int v = threadIdx.x;                             // 128
    float s = fc1_b[v];
    for (int o = 0; o < FDIM; o++) s += fc1_w[v * FDIM + o] * conv_b[o];
    g_bc[v] = s;
}

// ---------------- Wc GEMM: part[k3][v] = sum_o conv_w[o][k3]*fc1T[o][v] ----------------
__global__ void __launch_bounds__(256) k_wc_gemm(const float* __restrict__ conv_w) {
    __shared__ float As[2][16][128];
    __shared__ float Bs[2][16][128];
    int tid = threadIdx.x;
    int mb = blockIdx.x * 128;
    int ks = blockIdx.y;
    int tx = tid & 15, ty = tid >> 4;
    int lo = tid >> 5, lq = tid & 31;
    const float* gA = conv_w + (size_t)(ks * 128) * KDIM + mb;
    const float* gB = g_fc1T + (size_t)(ks * 128) * VDIM;
    float4 pa0, pa1, pb0, pb1;
    auto loadG = [&](int it) {
        pa0 = *(const float4*)(gA + (size_t)(it * 16 + lo) * KDIM + lq * 4);
        pa1 = *(const float4*)(gA + (size_t)(it * 16 + lo + 8) * KDIM + lq * 4);
        pb0 = *(const float4*)(gB + (it * 16 + lo) * VDIM + lq * 4);
        pb1 = *(const float4*)(gB + (it * 16 + lo + 8) * VDIM + lq * 4);
    };
    auto storeS = [&](int buf) {
        *(float4*)&As[buf][lo][lq * 4] = pa0;
        *(float4*)&As[buf][lo + 8][lq * 4] = pa1;
        *(float4*)&Bs[buf][lo][lq * 4] = pb0;
        *(float4*)&Bs[buf][lo + 8][lq * 4] = pb1;
    };
    loadG(0); storeS(0); __syncthreads();
    u64 c[32];
#pragma unroll
    for (int i = 0; i < 32; i++) c[i] = 0ull;
    const int NIT = 8;
    for (int it = 0; it < NIT; ++it) {
        int cur = it & 1;
        if (it + 1 < NIT) loadG(it + 1);
#pragma unroll
        for (int kk = 0; kk < 16; kk++) {
            float4 af0 = *(float4*)&As[cur][kk][ty * 8];
            float4 af1 = *(float4*)&As[cur][kk][ty * 8 + 4];
            float4 bf0 = *(float4*)&Bs[cur][kk][tx * 8];
            float4 bf1 = *(float4*)&Bs[cur][kk][tx * 8 + 4];
            u64 b[4] = { *(u64*)&bf0.x, *(u64*)&bf0.z, *(u64*)&bf1.x, *(u64*)&bf1.z };
            float a[8] = { af0.x, af0.y, af0.z, af0.w, af1.x, af1.y, af1.z, af1.w };
#pragma unroll
            for (int mi = 0; mi < 8; mi++) {
                u64 as = splat2(a[mi]);
#pragma unroll
                for (int p = 0; p < 4; p++) ffma2(c[mi * 4 + p], as, b[p]);
            }
        }
        if (it + 1 < NIT) { storeS((it + 1) & 1); __syncthreads(); }
    }
    float* out = g_wcp[ks];
#pragma unroll
    for (int mi = 0; mi < 8; mi++) {
        float2* orow = (float2*)(out + (size_t)(mb + ty * 8 + mi) * VDIM);
#pragma unroll
        for (int p = 0; p < 4; p++) orow[tx * 4 + p] = unpack2(c[mi * 4 + p]);
    }
}

// combine split-K partials, transpose to [v][k], convert to bf16 hi/lo
__global__ void __launch_bounds__(256) k_wc_finish() {
    __shared__ float ts[128][129];
    int k0 = blockIdx.x * 128;
    int t = threadIdx.x;
#pragma unroll 4
    for (int j = 0; j < 64; j++) {
        int idx = t + 256 * j;
        int kk = idx >> 7, v = idx & 127;
        size_t o = (size_t)(k0 + kk) * 128 + v;
        ts[kk][v] = g_wcp[0][o] + g_wcp[1][o] + g_wcp[2][o] + g_wcp[3][o];
    }
    __syncthreads();
#pragma unroll 4
    for (int j = 0; j < 64; j++) {
        int idx = t + 256 * j;
        int v = idx >> 7, kk = idx & 127;
        float val = ts[kk][v];
        __nv_bfloat16 h = __float2bfloat16(val);
        float hf = __bfloat162float(h);
        __nv_bfloat16 l = __float2bfloat16(val - hf);
        g_Wc_hi[(size_t)v * KDIM + k0 + kk] = h;
        g_Wc_lo[(size_t)v * KDIM + k0 + kk] = l;
    }
}

// ---------------- main GEMM via mma.sync bf16 hi/lo: f_partial = X @ Wc^T ----------------
// grid (64, 2): 128-row M tile x 128 cols, split-K halves of 1536, K chunk 64.
// smem per buffer: A_hi 16K | A_lo 16K | B_hi 16K | B_lo 16K = 64K; double = 128K.
#define SMA_H 0
#define SMA_L 16384
#define SMB_H 32768
#define SMB_L 49152
#define BUFSZ 65536
#define SM_TOTAL_MMA (2 * BUFSZ)

__global__ void __launch_bounds__(256, 1) k_gemm_mma(const float* __restrict__ X) {
    extern __shared__ __align__(128) char sm[];
    int tid = threadIdx.x;
    int warp = tid >> 5, lane = tid & 31;
    int mb = blockIdx.x * 128;
    int ksOff = blockIdx.y * 1536;
    const float* gX = X + (size_t)mb * KDIM + ksOff;

    float acc[16][4];
#pragma unroll
    for (int t = 0; t < 16; t++)
#pragma unroll
        for (int p = 0; p < 4; p++) acc[t][p] = 0.f;

    // staging registers for next chunk
    float4 pa[8];
    uint4 pbh[4], pbl[4];
    int aRow = tid >> 4, aG = tid & 15;       // A: 16 threads/row, float4 each
    int bRow = tid >> 3, bG = tid & 7;        // B: 8 threads/row, uint4 (8 bf16) each

    auto loadG = [&](int c) {
#pragma unroll
        for (int j = 0; j < 8; j++) {
            int row = aRow + j * 16;
            pa[j] = *(const float4*)(gX + (size_t)row * KDIM + c * 64 + aG * 4);
        }
#pragma unroll
        for (int j = 0; j < 4; j++) {
            int row = bRow + j * 32;
            size_t goff = (size_t)row * KDIM + ksOff + c * 64 + bG * 8;  // elements
            pbh[j] = *(const uint4*)((const char*)g_Wc_hi + goff * 2);
            pbl[j] = *(const uint4*)((const char*)g_Wc_lo + goff * 2);
        }
    };
    auto storeS = [&](int s) {
        char* base = sm + s * BUFSZ;
#pragma unroll
        for (int j = 0; j < 8; j++) {
            int row = aRow + j * 16;
            float4 v = pa[j];
            __nv_bfloat16 h0 = __float2bfloat16(v.x), h1 = __float2bfloat16(v.y);
            __nv_bfloat16 h2 = __float2bfloat16(v.z), h3 = __float2bfloat16(v.w);
            __nv_bfloat16 l0 = __float2bfloat16(v.x - __bfloat162float(h0));
            __nv_bfloat16 l1 = __float2bfloat16(v.y - __bfloat162float(h1));
            __nv_bfloat16 l2 = __float2bfloat16(v.z - __bfloat162float(h2));
            __nv_bfloat16 l3 = __float2bfloat16(v.w - __bfloat162float(h3));
            uint32_t hw0 = (uint32_t)__bfloat16_as_ushort(h0) | ((uint32_t)__bfloat16_as_ushort(h1) << 16);
            uint32_t hw1 = (uint32_t)__bfloat16_as_ushort(h2) | ((uint32_t)__bfloat16_as_ushort(h3) << 16);
            uint32_t lw0 = (uint32_t)__bfloat16_as_ushort(l0) | ((uint32_t)__bfloat16_as_ushort(l1) << 16);
            uint32_t lw1 = (uint32_t)__bfloat16_as_ushort(l2) | ((uint32_t)__bfloat16_as_ushort(l3) << 16);
            uint32_t off = swz((uint32_t)(row * 128 + aG * 8));
            *(uint2*)(base + SMA_H + off) = make_uint2(hw0, hw1);
            *(uint2*)(base + SMA_L + off) = make_uint2(lw0, lw1);
        }
#pragma unroll
        for (int j = 0; j < 4; j++) {
            int row = bRow + j * 32;
            uint32_t off = swz((uint32_t)(row * 128 + bG * 16));
            *(uint4*)(base + SMB_H + off) = pbh[j];
            *(uint4*)(base + SMB_L + off) = pbl[j];
        }
    };

    loadG(0); storeS(0); __syncthreads();

    // per-warp ldmatrix lane addressing
    int aLrow = warp * 16 + (lane & 15);
    int aLu = (lane >> 4) & 1;                 // second k8 half
    int bLn = (lane & 7) + ((lane >> 4) & 1) * 8;
    int bLu = (lane >> 3) & 1;

    const int NCH = 24;
    for (int c = 0; c < NCH; c++) {
        int s = c & 1;
        if (c + 1 < NCH) loadG(c + 1);
        uint32_t baseA_h = smem_u32(sm + s * BUFSZ + SMA_H);
        uint32_t baseA_l = baseA_h + (SMA_L - SMA_H);
        uint32_t baseB_h = baseA_h + (SMB_H - SMA_H);
        uint32_t baseB_l = baseA_h + (SMB_L - SMA_H);
#pragma unroll
        for (int kst = 0; kst < 4; kst++) {
            uint32_t aOff = swz((uint32_t)(aLrow * 128 + kst * 32 + aLu * 16));
            uint32_t ah[4], al[4];
            ldsm4(ah[0], ah[1], ah[2], ah[3], baseA_h + aOff);
            ldsm4(al[0], al[1], al[2], al[3], baseA_l + aOff);
            uint32_t bOff = swz((uint32_t)(bLn * 128 + kst * 32 + bLu * 16));
#pragma unroll
            for (int nt = 0; nt < 8; nt++) {
                uint32_t bh0, bh1, bh2, bh3, bl0, bl1, bl2, bl3;
                uint32_t bo = swz((uint32_t)((nt * 16 + bLn) * 128 + kst * 32 + bLu * 16));
                ldsm4(bh0, bh1, bh2, bh3, baseB_h + bo);
                ldsm4(bl0, bl1, bl2, bl3, baseB_l + bo);
                mma16816(acc[2 * nt], ah, bh0, bh1);
                mma16816(acc[2 * nt], ah, bl0, bl1);
                mma16816(acc[2 * nt], al, bh0, bh1);
                mma16816(acc[2 * nt + 1], ah, bh2, bh3);
                mma16816(acc[2 * nt + 1], ah, bl2, bl3);
                mma16816(acc[2 * nt + 1], al, bh2, bh3);
            }
            (void)bOff;
        }
        __syncthreads();
        if (c + 1 < NCH) { storeS(s ^ 1); __syncthreads(); }
    }

    // epilogue: frag layout m16n8: rows lane>>2 and +8; cols (lane&3)*2 + {0,1}
    int m0 = mb + warp * 16 + (lane >> 2);
    float* o0 = g_vp[blockIdx.y] + (size_t)m0 * VDIM;
#pragma unroll
    for (int t = 0; t < 16; t++) {
        int n = t * 8 + (lane & 3) * 2;
        *(float2*)(o0 + n) = make_float2(acc[t][0], acc[t][1]);
        *(float2*)(o0 + 8 * VDIM + n) = make_float2(acc[t][2], acc[t][3]);
    }
}

// ---------------- combine split-K + bias, write f, L2-normalize ----------------
__global__ void k_combine(float* __restrict__ f_out) {
    int row = blockIdx.x;
    int v = threadIdx.x;                             // 128
    size_t i = (size_t)row * VDIM + v;
    float x = g_vp[0][i] + g_vp[1][i] + g_bc[v];
    f_out[i] = x;
    float ss = x * x;
#pragma unroll
    for (int o = 16; o > 0; o >>= 1) ss += __shfl_xor_sync(0xffffffffu, ss, o);
    __shared__ float sred[4];
    if ((v & 31) == 0) sred[v >> 5] = ss;
    __syncthreads();
    float tot = sred[0] + sred[1] + sred[2] + sred[3];
    float inv = 1.0f / fmaxf(sqrtf(tot), 1e-12f);
    g_fn[i] = x * inv;
}

// ---------------- affinity: A[b] = fn fn^T (symmetric), also emit E = exp(TEMP*A) ----------------
__global__ void __launch_bounds__(256) k_aff(float* __restrict__ A_out) {
    __shared__ float As[2][128][20];
    __shared__ float Bs[2][16][132];
    int t = blockIdx.x;                  // 0:(0,0) 1:(1,1) 2:(0,1)+mirror
    int b = blockIdx.y;
    int mb = (t == 1) ? 128 : 0;
    int nb = (t == 0) ? 0 : 128;
    const float* fb = g_fn + (size_t)b * NN * VDIM;
    int tid = threadIdx.x, tx = tid & 15, ty = tid >> 4;
    int ar = tid >> 1, ah = tid & 1;
    const float* gA = fb + (size_t)(mb + ar) * VDIM + ah * 8;
    const float* gB = fb + (size_t)(nb + ar) * VDIM + ah * 8;
    float4 pa0, pa1, pb0, pb1;
    auto loadG = [&](int it) {
        pa0 = *(const float4*)(gA + it * 16);
        pa1 = *(const float4*)(gA + it * 16 + 4);
        pb0 = *(const float4*)(gB + it * 16);
        pb1 = *(const float4*)(gB + it * 16 + 4);
    };
    auto storeS = [&](int buf) {
        *(float4*)&As[buf][ar][ah * 8] = pa0;
        *(float4*)&As[buf][ar][ah * 8 + 4] = pa1;
        Bs[buf][ah * 8 + 0][ar] = pb0.x;  Bs[buf][ah * 8 + 1][ar] = pb0.y;
        Bs[buf][ah * 8 + 2][ar] = pb0.z;  Bs[buf][ah * 8 + 3][ar] = pb0.w;
        Bs[buf][ah * 8 + 4][ar] = pb1.x;  Bs[buf][ah * 8 + 5][ar] = pb1.y;
        Bs[buf][ah * 8 + 6][ar] = pb1.z;  Bs[buf][ah * 8 + 7][ar] = pb1.w;
    };
    loadG(0); storeS(0); __syncthreads();
    u64 c[32];
#pragma unroll
    for (int i = 0; i < 32; i++) c[i] = 0ull;
    const int NIT = 8;
    for (int it = 0; it < NIT; ++it) {
        int cur = it & 1;
        if (it + 1 < NIT) loadG(it + 1);
#pragma unroll
        for (int kk = 0; kk < 16; kk++) {
            float4 bf0 = *(float4*)&Bs[cur][kk][tx * 8];
            float4 bf1 = *(float4*)&Bs[cur][kk][tx * 8 + 4];
            u64 b2[4] = { *(u64*)&bf0.x, *(u64*)&bf0.z, *(u64*)&bf1.x, *(u64*)&bf1.z };
#pragma unroll
            for (int mi = 0; mi < 8; mi++) {
                u64 as = splat2(As[cur][ty * 8 + mi][kk]);
#pragma unroll
                for (int p = 0; p < 4; p++) ffma2(c[mi * 4 + p], as, b2[p]);
            }
        }
        if (it + 1 < NIT) { storeS((it + 1) & 1); __syncthreads(); }
    }
    float* Ab = A_out + (size_t)b * NN * NN;
    float* Eb = g_E + (size_t)b * NN * NN;
#pragma unroll
    for (int mi = 0; mi < 8; mi++) {
        int m = mb + ty * 8 + mi;
#pragma unroll
        for (int p = 0; p < 4; p++) {
            float2 val = unpack2(c[mi * 4 + p]);
            int n = nb + tx * 8 + 2 * p;
            float e0 = __expf(TEMP * val.x);
            float e1 = __expf(TEMP * val.y);
            *(float2*)&Ab[(size_t)m * NN + n] = val;
            *(float2*)&Eb[(size_t)m * NN + n] = make_float2(e0, e1);
            if (t == 2) {
                Ab[(size_t)n * NN + m] = val.x;
                Ab[(size_t)(n + 1) * NN + m] = val.y;
                Eb[(size_t)n * NN + m] = e0;
                Eb[(size_t)(n + 1) * NN + m] = e1;
            }
        }
    }
}

// ---------------- transpose drop2 (per batch, 32x32 tiles) ----------------
__global__ void k_d2t(const float* __restrict__ d2) {
    __shared__ float ts[32][33];
    int b = blockIdx.x;
    int tile = blockIdx.y;
    int r0 = (tile >> 3) * 32, c0 = (tile & 7) * 32;
    const float* src = d2 + (size_t)b * NN * NN;
    float* dst = g_d2T + (size_t)b * NN * NN;
    int lx = threadIdx.x & 31, ly = threadIdx.x >> 5;   // 32 x 8
#pragma unroll
    for (int j = 0; j < 32; j += 8)
        ts[ly + j][lx] = src[(size_t)(r0 + ly + j) * NN + c0 + lx];
    __syncthreads();
#pragma unroll
    for (int j = 0; j < 32; j += 8)
        dst[(size_t)(c0 + ly + j) * NN + r0 + lx] = ts[lx][ly + j];
}

// ---------------- stats: W1_i, W2_i -> F1, F2 (no max needed; exp bounded) ----------------
__global__ void k_stats(const float* __restrict__ d1, const float* __restrict__ d2) {
    __shared__ float s1[8][32], s2[8][32];
    int b = blockIdx.x, ib = blockIdx.y * 32;
    int ti = threadIdx.x & 31, ks = threadIdx.x >> 5;
    int i = ib + ti;
    const float* E  = g_E + (size_t)b * NN * NN;
    const float* D1 = d1 + (size_t)b * NN * NN;
    const float* D2 = d2 + (size_t)b * NN * NN;
    float a1 = 0.f, a2 = 0.f;
#pragma unroll 4
    for (int kk = 0; kk < 32; kk++) {
        int k = ks * 32 + kk;
        float e = E[(size_t)k * NN + i];
        if (k != i) {
            a1 += e * D1[(size_t)k * NN + i];
            a2 += e * D2[(size_t)k * NN + i];
        }
    }
    s1[ks][ti] = a1; s2[ks][ti] = a2;
    __syncthreads();
    if (ks == 0) {
        float W1 = 0.f, W2 = 0.f;
#pragma unroll
        for (int w = 0; w < 8; w++) { W1 += s1[w][ti]; W2 += s2[w][ti]; }
        g_F1[b * NN + i] = 1.0f / fmaxf(W1, 1e-30f);
        g_F2[b * NN + i] = 1.0f / fmaxf(W2, 1e-30f);
    }
}

// ---------------- loss: diag_i = F1_i * sum_{k!=i} E_ik^2 * d2[i][k] * d1[k][i] * F2_k ----------------
__global__ void k_loss(const float* __restrict__ d1) {
    __shared__ float sp[8][32];
    int b = blockIdx.x, ib = blockIdx.y * 32;
    int ti = threadIdx.x & 31, ks = threadIdx.x >> 5;
    int i = ib + ti;
    const float* E  = g_E + (size_t)b * NN * NN;
    const float* D1 = d1 + (size_t)b * NN * NN;
    const float* T2 = g_d2T + (size_t)b * NN * NN;
    float acc = 0.f;
#pragma unroll 4
    for (int kk = 0; kk < 32; kk++) {
        int k = ks * 32 + kk;
        float e = E[(size_t)k * NN + i];                 // E symmetric = E[i][k]
        float t = e * e * T2[(size_t)k * NN + i] * D1[(size_t)k * NN + i] * g_F2[b * NN + k];
        if (k != i) acc += t;
    }
    sp[ks][ti] = acc;
    __syncthreads();
    if (threadIdx.x < 32) {
        float v = 0.f;
#pragma unroll
        for (int w = 0; w < 8; w++) v += sp[w][ti];
        v *= g_F1[b * NN + i];
#pragma unroll
        for (int o = 16; o > 0; o >>= 1) v += __shfl_xor_sync(0xffffffffu, v, o);
        if (ti == 0) g_lp2[b * 8 + blockIdx.y] = v;
    }
}

__global__ void k_final(float* __restrict__ out_loss) {
    __shared__ float sr[8];
    int t = threadIdx.x;                                 // 256
    float v = g_lp2[t];
#pragma unroll
    for (int o = 16; o > 0; o >>= 1) v += __shfl_xor_sync(0xffffffffu, v, o);
    if ((t & 31) == 0) sr[t >> 5] = v;
    __syncthreads();
    if (t == 0) {
        float s = 0.f;
#pragma unroll
        for (int w = 0; w < 8; w++) s += sr[w];
        out_loss[0] = -s / (float)(NBATCH * NN);
    }
}

// ---------------- launch ----------------
extern "C" void kernel_launch(void* const* d_in, const int* in_sizes, int n_in,
                              void* d_out, int out_size) {
    const float* x      = (const float*)d_in[0];
    const float* conv_w = (const float*)d_in[1];
    const float* conv_b = (const float*)d_in[2];
    const float* fc1_w  = (const float*)d_in[3];
    const float* fc1_b  = (const float*)d_in[4];
    const float* drop1  = (const float*)d_in[5];
    const float* drop2  = (const float*)d_in[6];
    float* out_f = (float*)d_out;
    float* out_A = out_f + (size_t)BN * VDIM;
    float* out_loss = out_A + (size_t)NBATCH * NN * NN;

    cudaFuncSetAttribute(k_gemm_mma, cudaFuncAttributeMaxDynamicSharedMemorySize, SM_TOTAL_MMA);

    k_prep_fc1T<<<256, 256>>>(fc1_w);
    k_bc<<<1, 128>>>(fc1_w, conv_b, fc1_b);
    k_wc_gemm<<<dim3(24, 4), 256>>>(conv_w);
    k_wc_finish<<<24, 256>>>();
    k_gemm_mma<<<dim3(64, 2), 256, SM_TOTAL_MMA>>>(x);
    k_combine<<<BN, 128>>>(out_f);
    k_aff<<<dim3(3, NBATCH), 256>>>(out_A);
    k_d2t<<<dim3(NBATCH, 64), 256>>>(drop2);
    k_stats<<<dim3(NBATCH, 8), 256>>>(drop1, drop2);
    k_loss<<<dim3(NBATCH, 8), 256>>>(drop1);
    k_final<<<1, 256>>>(out_loss);
}